// round 8
// baseline (speedup 1.0000x reference)
#include <cuda_runtime.h>
#include <cstdint>

#define BATCH   256
#define TSTEPS  1000
#define LIN     30
#define KW      7
#define LO      24
#define JDIM    384
#define NOUT    35
#define NTHREADS 512     // warps 0-11: B (r=warp,o=lane) | 12-14: A(4 pos)+out32-34 | 15: C
#define CHUNK   50
#define NCHUNK  (TSTEPS / CHUNK)
#define XS_LEN  (CHUNK * LIN + 4)   // +pad: A reads 2 floats past the last row

typedef unsigned long long ull;

__device__ __forceinline__ uint32_t smem_u32(const void* p) {
    return (uint32_t)__cvta_generic_to_shared(p);
}
__device__ __forceinline__ void cp_async8(uint32_t dst, const void* src) {
    asm volatile("cp.async.ca.shared.global [%0], [%1], 8;" :: "r"(dst), "l"(src));
}
__device__ __forceinline__ void cp_commit() { asm volatile("cp.async.commit_group;"); }
__device__ __forceinline__ void cp_wait1()  { asm volatile("cp.async.wait_group 1;" ::: "memory"); }
__device__ __forceinline__ void cp_wait0()  { asm volatile("cp.async.wait_group 0;" ::: "memory"); }

__device__ __forceinline__ ull pk(float a, float b) {
    ull r; asm("mov.b64 %0, {%1,%2};" : "=l"(r) : "f"(a), "f"(b)); return r;
}
__device__ __forceinline__ void upk(ull v, float& a, float& b) {
    asm("mov.b64 {%0,%1}, %2;" : "=f"(a), "=f"(b) : "l"(v));
}
__device__ __forceinline__ ull f2fma(ull a, ull b, ull c) {
    ull d; asm("fma.rn.f32x2 %0, %1, %2, %3;" : "=l"(d) : "l"(a), "l"(b), "l"(c)); return d;
}
__device__ __forceinline__ ull f2mul(ull a, ull b) {
    ull d; asm("mul.rn.f32x2 %0, %1, %2;" : "=l"(d) : "l"(a), "l"(b)); return d;
}

// One pipelined iteration: C(t-2), B/dot32(t-1), A(t); single barrier.
// A writes spk[pa]; B & dot32 read spk[pa^1], B writes part[pa^1]; C reads part[pa].
#define STEP(PA, XROW, DOA, DOB, DOC)                                          \
  {                                                                            \
    const int pa_ = (PA);                                                      \
    if (wid < 12) {                                                            \
      if (DOB) {                                                               \
        uint32_t sp = spkB + (uint32_t)((pa_ ^ 1) * (JDIM * 4));               \
        ull a0 = 0ull, a1 = 0ull;                                              \
        _Pragma("unroll")                                                      \
        for (int k = 0; k < 16; k += 2) {                                      \
          ull s0, s1;                                                          \
          asm("ld.shared.v2.u64 {%0,%1}, [%2];"                                \
              : "=l"(s0), "=l"(s1) : "r"(sp + (uint32_t)(k * 8)));             \
          a0 = f2fma(s0, w2[k],     a0);                                       \
          a1 = f2fma(s1, w2[k + 1], a1);                                       \
        }                                                                      \
        float x0_, x1_, y0_, y1_;                                              \
        upk(a0, x0_, x1_);                                                     \
        upk(a1, y0_, y1_);                                                     \
        part[pa_ ^ 1][wid][lane] = (x0_ + x1_) + (y0_ + y1_);                  \
      }                                                                        \
    } else if (wid < 15) {                                                     \
      float d32new = 0.f;                                                      \
      if (DOB) { /* dot for output o32, step t-1 */                            \
        uint32_t sa = spkA + (uint32_t)((pa_ ^ 1) * (JDIM * 4));               \
        ull s0, s1, s2, s3, s4, s5;                                            \
        asm("ld.shared.v2.u64 {%0,%1}, [%2];" : "=l"(s0), "=l"(s1) : "r"(sa));       \
        asm("ld.shared.v2.u64 {%0,%1}, [%2];" : "=l"(s2), "=l"(s3) : "r"(sa + 16));  \
        asm("ld.shared.v2.u64 {%0,%1}, [%2];" : "=l"(s4), "=l"(s5) : "r"(sa + 32));  \
        ull aa = f2mul(s0, w32[0]);                                            \
        aa = f2fma(s1, w32[1], aa);                                            \
        aa = f2fma(s2, w32[2], aa);                                            \
        aa = f2fma(s3, w32[3], aa);                                            \
        aa = f2fma(s4, w32[4], aa);                                            \
        aa = f2fma(s5, w32[5], aa);                                            \
        float lo_, hi_;                                                        \
        upk(aa, lo_, hi_);                                                     \
        float v = lo_ + hi_;                                                   \
        v += __shfl_down_sync(0xFFFFFFFFu, v, 16);                             \
        v += __shfl_down_sync(0xFFFFFFFFu, v, 8);                              \
        v += __shfl_down_sync(0xFFFFFFFFu, v, 4);                              \
        v += __shfl_down_sync(0xFFFFFFFFu, v, 2);                              \
        v += __shfl_down_sync(0xFFFFFFFFu, v, 1);                              \
        d32new = v;                                                            \
      }                                                                        \
      if ((DOC) && lane == 0) { /* LIF2 for step t-2, output o32 */            \
        float c2 = __fadd_rn(d32prev, bias32);                                 \
        float r2 = (mem232 > 1.0f) ? 1.0f : 0.0f;                              \
        mem232 = __fsub_rn(__fadd_rn(__fmul_rn(0.9f, mem232), c2), r2);        \
        acc32 += (double)mem232;                                               \
      }                                                                        \
      if (DOB) d32prev = d32new;                                               \
      if (DOA) { /* conv + LIF1 for 4 positions, step t */                     \
        const float2* xq = (const float2*)((XROW) + 4 * p);                    \
        float xv[12];                                                          \
        _Pragma("unroll")                                                      \
        for (int i = 0; i < 6; ++i) {                                          \
          float2 f = xq[i];                                                    \
          xv[2 * i] = f.x; xv[2 * i + 1] = f.y;                                \
        }                                                                      \
        float sp4[4];                                                          \
        _Pragma("unroll")                                                      \
        for (int d = 0; d < 4; ++d) {                                          \
          float s = __fmul_rn(xv[d], wc[0]);                                   \
          _Pragma("unroll")                                                    \
          for (int k = 1; k < KW; ++k) s = __fmaf_rn(xv[d + k], wc[k], s);     \
          float c1 = __fadd_rn(s, bc);                                         \
          float r1 = (m1[d] > 1.0f) ? 1.0f : 0.0f;                             \
          m1[d] = __fsub_rn(__fadd_rn(__fmul_rn(0.9f, m1[d]), c1), r1);        \
          sp4[d] = (m1[d] > 1.0f) ? 1.0f : 0.0f;                               \
        }                                                                      \
        *(float4*)&spk[pa_][jA] = make_float4(sp4[0], sp4[1], sp4[2], sp4[3]); \
      }                                                                        \
    } else { /* wid == 15: C for outputs 0-31 */                               \
      if (DOC) {                                                               \
        float c2 = part[pa_][0][lane];                                         \
        _Pragma("unroll")                                                      \
        for (int rr = 1; rr < 12; ++rr) c2 += part[pa_][rr][lane];             \
        c2 = __fadd_rn(c2, bias2);                                             \
        float r2 = (mem2 > 1.0f) ? 1.0f : 0.0f;                                \
        mem2 = __fsub_rn(__fadd_rn(__fmul_rn(0.9f, mem2), c2), r2);            \
        acc += (double)mem2;                                                   \
      }                                                                        \
    }                                                                          \
    __syncthreads();                                                           \
  }

__global__ __launch_bounds__(NTHREADS, 2)
void snn_kernel(const float* __restrict__ x,
                const float* __restrict__ conv_w,
                const float* __restrict__ conv_b,
                const float* __restrict__ fc_w,
                const float* __restrict__ fc_b,
                float* __restrict__ out)
{
    __shared__ __align__(16) float xs[2][XS_LEN];
    __shared__ __align__(16) float spk[2][JDIM];
    __shared__ __align__(16) float part[2][12][32];

    const int b    = blockIdx.x;
    const int tid  = threadIdx.x;
    const int wid  = tid >> 5;
    const int lane = tid & 31;

    // ---- B state (warps 0-11): r = wid, o = lane; JT=32 weights packed ----
    ull w2[16];
    if (wid < 12) {
        #pragma unroll
        for (int k = 0; k < 16; ++k)
            w2[k] = pk(fc_w[lane * JDIM + wid * 32 + 2 * k],
                       fc_w[lane * JDIM + wid * 32 + 2 * k + 1]);
    }
    const uint32_t spkB = smem_u32(&spk[0][0]) + (uint32_t)(wid < 12 ? wid * 128 : 0);

    // ---- A state (warps 12-14): 4 positions each; plus output 32+(wid-12) ----
    const bool aTh  = (wid >= 12) && (wid < 15);
    const int  aidx = tid - 384;                 // 0..95 for A threads
    const int  ch   = aidx / 6;
    const int  p    = aidx % 6;                  // positions 4p..4p+3
    const int  jA   = ch * LO + 4 * p;
    float wc[KW], bc = 0.f;
    float m1[4] = {0.f, 0.f, 0.f, 0.f};
    ull   w32[6];
    float d32prev = 0.f, mem232 = 0.f, bias32 = 0.f;
    double acc32 = 0.0;
    int o32 = 0;
    if (aTh) {
        #pragma unroll
        for (int k = 0; k < KW; ++k) wc[k] = conv_w[ch * KW + k];
        bc  = conv_b[ch];
        o32 = 32 + (wid - 12);
        #pragma unroll
        for (int m = 0; m < 6; ++m)
            w32[m] = pk(fc_w[o32 * JDIM + lane * 12 + 2 * m],
                        fc_w[o32 * JDIM + lane * 12 + 2 * m + 1]);
        if (lane == 0) bias32 = fc_b[o32];
    }
    const uint32_t spkA = smem_u32(&spk[0][0]) + (uint32_t)(lane * 48);

    // ---- C state (warp 15): output o = lane (0-31) ----
    float  bias2 = 0.f, mem2 = 0.f;
    double acc   = 0.0;
    if (wid == 15) bias2 = fc_b[lane];

    const float* xb = x + (size_t)b * TSTEPS * LIN;

    // ---- prefetch chunk 0 (A threads: 750 x 8B over 96 threads) ----
    if (aTh) {
        uint32_t sbase = smem_u32(&xs[0][0]);
        for (int i = aidx; i < CHUNK * LIN / 2; i += 96)
            cp_async8(sbase + i * 8, xb + i * 2);
    }
    cp_commit();

    for (int chunk = 0; chunk < NCHUNK; ++chunk) {
        const int buf = chunk & 1;
        if (chunk + 1 < NCHUNK) {
            if (aTh) {
                uint32_t sbase   = smem_u32(&xs[buf ^ 1][0]);
                const float* src = xb + (size_t)(chunk + 1) * CHUNK * LIN;
                for (int i = aidx; i < CHUNK * LIN / 2; i += 96)
                    cp_async8(sbase + i * 8, src + i * 2);
            }
            cp_commit();
            cp_wait1();
        } else {
            cp_wait0();
        }
        __syncthreads();

        const float* xrow = &xs[buf][0];
        if (chunk == 0) {
            #pragma unroll 2
            for (int tc = 0; tc < CHUNK; ++tc)
                STEP(tc & 1, xrow + tc * LIN, true, tc >= 1, tc >= 2);
        } else {
            #pragma unroll 2
            for (int tc = 0; tc < CHUNK; ++tc)
                STEP(tc & 1, xrow + tc * LIN, true, true, true);
        }
    }

    // ---- drain: t=1000 (B/dot32(999), C(998)); t=1001 (C(999)) ----
    STEP(0, &xs[0][0], false, true, true);
    STEP(1, &xs[0][0], false, false, true);

    if (wid == 15)
        out[b * NOUT + lane] = (float)(acc * (1.0 / (double)TSTEPS));
    if (aTh && lane == 0)
        out[b * NOUT + o32] = (float)(acc32 * (1.0 / (double)TSTEPS));
}

extern "C" void kernel_launch(void* const* d_in, const int* in_sizes, int n_in,
                              void* d_out, int out_size)
{
    const float* x      = (const float*)d_in[0];
    const float* conv_w = (const float*)d_in[1];
    const float* conv_b = (const float*)d_in[2];
    const float* fc_w   = (const float*)d_in[3];
    const float* fc_b   = (const float*)d_in[4];
    snn_kernel<<<BATCH, NTHREADS>>>(x, conv_w, conv_b, fc_w, fc_b, (float*)d_out);
}

// round 9
// speedup vs baseline: 2.2426x; 2.2426x over previous
#include <cuda_runtime.h>
#include <cstdint>

#define BATCH   256
#define TSTEPS  1000
#define LIN     30
#define KW      7
#define LO      24
#define JDIM    384
#define NOUT    35
#define NTHREADS 448     // warps 0-11: A + B(r=wid,o=lane) | w12: B-extra + C32-34 | w13: C + B-extra tail
#define CHUNK   50
#define NCHUNK  (TSTEPS / CHUNK)
#define ROWP    32       // padded x row stride (floats) -> 128B aligned rows
#define SPKG    36       // padded spike group stride (floats) -> kills 128B-stride bank conflicts
#define PCOL    36       // part columns (0-31 main, 32-34 extra)

typedef unsigned long long ull;

__device__ __forceinline__ uint32_t smem_u32(const void* p) {
    return (uint32_t)__cvta_generic_to_shared(p);
}
__device__ __forceinline__ void cp_async8(uint32_t dst, const void* src) {
    asm volatile("cp.async.ca.shared.global [%0], [%1], 8;" :: "r"(dst), "l"(src));
}
__device__ __forceinline__ void cp_commit() { asm volatile("cp.async.commit_group;"); }
__device__ __forceinline__ void cp_wait1()  { asm volatile("cp.async.wait_group 1;" ::: "memory"); }
__device__ __forceinline__ void cp_wait0()  { asm volatile("cp.async.wait_group 0;" ::: "memory"); }

__device__ __forceinline__ ull pk(float a, float b) {
    ull r; asm("mov.b64 %0, {%1,%2};" : "=l"(r) : "f"(a), "f"(b)); return r;
}
__device__ __forceinline__ void upk(ull v, float& a, float& b) {
    asm("mov.b64 {%0,%1}, %2;" : "=f"(a), "=f"(b) : "l"(v));
}
__device__ __forceinline__ ull f2fma(ull a, ull b, ull c) {
    ull d; asm("fma.rn.f32x2 %0, %1, %2, %3;" : "=l"(d) : "l"(a), "l"(b), "l"(c)); return d;
}

// One pipelined iteration: C(t-2), B(t-1), A(t); single barrier.
// A writes spk[pa]; B reads spk[pa^1], writes part[pa^1]; C reads part[pa].
#define STEP(PA, XROWBASE, DOA, DOB, DOC)                                      \
  {                                                                            \
    const int pa_ = (PA);                                                      \
    if ((DOC) && cTh) {                                                        \
      float c2 = part[pa_][0][ccol];                                           \
      _Pragma("unroll")                                                        \
      for (int rr = 1; rr < 12; ++rr) c2 += part[pa_][rr][ccol];               \
      c2 = __fadd_rn(c2, bias2);                                               \
      float r2 = (mem2 > 1.0f) ? 1.0f : 0.0f;                                  \
      mem2 = __fsub_rn(__fadd_rn(__fmul_rn(0.9f, mem2), c2), r2);              \
      acc += (double)mem2;                                                     \
    }                                                                          \
    if ((DOB) && bTh) {                                                        \
      uint32_t sp = pa_ ? spkB0 : spkB1;        /* spk[pa^1] */                \
      ull a0 = 0ull, a1 = 0ull;                                                \
      _Pragma("unroll")                                                        \
      for (int k = 0; k < 16; k += 2) {                                        \
        ull s0, s1;                                                            \
        asm("ld.shared.v2.u64 {%0,%1}, [%2];"                                  \
            : "=l"(s0), "=l"(s1) : "r"(sp + (uint32_t)(k * 8)));               \
        a0 = f2fma(s0, w2[k],     a0);                                         \
        a1 = f2fma(s1, w2[k + 1], a1);                                         \
      }                                                                        \
      float x0_, x1_, y0_, y1_;                                                \
      upk(a0, x0_, x1_);                                                       \
      upk(a1, y0_, y1_);                                                       \
      *(pa_ ? bdst0 : bdst1) = (x0_ + x1_) + (y0_ + y1_);  /* part[pa^1] */    \
    }                                                                          \
    if ((DOA) && aTh) {                                                        \
      float xv = (XROWBASE)[lane];                                             \
      float s  = __fmul_rn(__shfl_sync(0xFFFFFFFFu, xv, pos), wc[0]);          \
      _Pragma("unroll")                                                        \
      for (int k = 1; k < KW; ++k)                                             \
        s = __fmaf_rn(__shfl_sync(0xFFFFFFFFu, xv, pos + k), wc[k], s);        \
      float c1 = __fadd_rn(s, bc);                                             \
      float r1 = (mem1 > 1.0f) ? 1.0f : 0.0f;                                  \
      mem1 = __fsub_rn(__fadd_rn(__fmul_rn(0.9f, mem1), c1), r1);              \
      spk[pa_][sIdx] = (mem1 > 1.0f) ? 1.0f : 0.0f;                            \
    }                                                                          \
    __syncthreads();                                                           \
  }

__global__ __launch_bounds__(NTHREADS, 2)
void snn_kernel(const float* __restrict__ x,
                const float* __restrict__ conv_w,
                const float* __restrict__ conv_b,
                const float* __restrict__ fc_w,
                const float* __restrict__ fc_b,
                float* __restrict__ out)
{
    __shared__ __align__(128) float xs[2][CHUNK * ROWP];  // 12.8 KB, rows 128B-aligned
    __shared__ __align__(16)  float spk[2][12 * SPKG];    // padded-stride spike groups
    __shared__ __align__(16)  float part[2][12][PCOL];

    const int b    = blockIdx.x;
    const int tid  = threadIdx.x;
    const int wid  = tid >> 5;
    const int lane = tid & 31;

    // ---- A state (warps 0-11): thread tid<384 owns position j=tid (ch=j/24, pos=j%24) ----
    const bool aTh = (wid < 12);
    const int  pos = tid % LO;
    const int  sIdx = wid * SPKG + lane;       // group = tid>>5, padded stride
    float wc[KW], bc = 0.f, mem1 = 0.f;
    if (aTh) {
        const int ch = tid / LO;
        #pragma unroll
        for (int k = 0; k < KW; ++k) wc[k] = conv_w[ch * KW + k];
        bc = conv_b[ch];
    }

    // ---- B state: warps 0-11 -> (r=wid, o=lane); threads 384-419 -> (r=i/3, o=32+i%3) ----
    bool bTh = false;
    int  brow = 0, bcol = 0;
    if (wid < 12)            { bTh = true; brow = wid;              bcol = lane; }
    else if (tid < 384 + 36) { bTh = true; int i = tid - 384; brow = i / 3; bcol = 32 + i % 3; }
    ull w2[16];
    if (bTh) {
        #pragma unroll
        for (int k = 0; k < 16; ++k)
            w2[k] = pk(fc_w[bcol * JDIM + brow * 32 + 2 * k],
                       fc_w[bcol * JDIM + brow * 32 + 2 * k + 1]);
    }
    const uint32_t spkB0 = smem_u32(&spk[0][0]) + (uint32_t)(brow * SPKG * 4);
    const uint32_t spkB1 = spkB0 + (uint32_t)(12 * SPKG * 4);
    float* const bdst0 = &part[0][brow][bcol];
    float* const bdst1 = &part[1][brow][bcol];

    // ---- C state: warp 13 -> outputs 0-31; warp 12 lanes 29-31 -> outputs 32-34 ----
    bool cTh = false;
    int  ccol = 0;
    if (wid == 13)                    { cTh = true; ccol = lane; }
    else if (wid == 12 && lane >= 29) { cTh = true; ccol = 32 + (lane - 29); }
    float  bias2 = 0.f, mem2 = 0.f;
    double acc   = 0.0;
    if (cTh) bias2 = fc_b[ccol];

    const float* xb = x + (size_t)b * TSTEPS * LIN;

    // ---- prefetch chunk 0 into padded rows (threads 384-447) ----
    if (tid >= 384) {
        uint32_t sbase = smem_u32(&xs[0][0]);
        for (int i = tid - 384; i < CHUNK * 15; i += 64) {
            int t = i / 15, c = i - t * 15;
            cp_async8(sbase + (uint32_t)(t * ROWP * 4 + c * 8), xb + t * LIN + c * 2);
        }
    }
    cp_commit();

    for (int chunk = 0; chunk < NCHUNK; ++chunk) {
        const int buf = chunk & 1;
        if (chunk + 1 < NCHUNK) {
            if (tid >= 384) {
                uint32_t sbase   = smem_u32(&xs[buf ^ 1][0]);
                const float* src = xb + (size_t)(chunk + 1) * CHUNK * LIN;
                for (int i = tid - 384; i < CHUNK * 15; i += 64) {
                    int t = i / 15, c = i - t * 15;
                    cp_async8(sbase + (uint32_t)(t * ROWP * 4 + c * 8), src + t * LIN + c * 2);
                }
            }
            cp_commit();
            cp_wait1();
        } else {
            cp_wait0();
        }
        __syncthreads();

        const float* xbase = &xs[buf][0];
        if (chunk == 0) {
            #pragma unroll 2
            for (int tc = 0; tc < CHUNK; ++tc)
                STEP(tc & 1, xbase + tc * ROWP, true, tc >= 1, tc >= 2);
        } else {
            #pragma unroll 2
            for (int tc = 0; tc < CHUNK; ++tc)
                STEP(tc & 1, xbase + tc * ROWP, true, true, true);
        }
    }

    // ---- drain: t=1000 (B(999), C(998)); t=1001 (C(999)) ----
    STEP(0, &xs[0][0], false, true, true);
    STEP(1, &xs[0][0], false, false, true);

    if (cTh)
        out[b * NOUT + ccol] = (float)(acc * (1.0 / (double)TSTEPS));
}

extern "C" void kernel_launch(void* const* d_in, const int* in_sizes, int n_in,
                              void* d_out, int out_size)
{
    const float* x      = (const float*)d_in[0];
    const float* conv_w = (const float*)d_in[1];
    const float* conv_b = (const float*)d_in[2];
    const float* fc_w   = (const float*)d_in[3];
    const float* fc_b   = (const float*)d_in[4];
    snn_kernel<<<BATCH, NTHREADS>>>(x, conv_w, conv_b, fc_w, fc_b, (float*)d_out);
}